// round 6
// baseline (speedup 1.0000x reference)
#include <cuda_runtime.h>

#define BB 256
#define SS 512
#define TT 128

// Scratch (no allocations allowed in kernel_launch)
__device__ __align__(16) float g_ET[TT * TT];  // g_ET[t*TT+i] = exp(trans[i][t])
__device__ float g_gold[BB];
__device__ float g_logZ[BB];
__device__ int   g_tagStride;      // 1 = int32 tags, 2 = int64 tags

// ---------------------------------------------------------------------------
// Kernel 0: detect tag dtype (odd 32-bit words all zero => int64 buffer)
// ---------------------------------------------------------------------------
__global__ void detect_tags_kernel(const unsigned int* __restrict__ tags32) {
    unsigned int acc = 0;
    for (int i = threadIdx.x; i < 256; i += 32)
        acc |= tags32[2 * i + 1];
    #pragma unroll
    for (int o = 16; o > 0; o >>= 1)
        acc |= __shfl_xor_sync(0xffffffffu, acc, o);
    if (threadIdx.x == 0) g_tagStride = (acc == 0u) ? 2 : 1;
}

// ---------------------------------------------------------------------------
// Kernel 1: g_ET[t][i] = exp(trans[i][t])   (transposed: column t contiguous)
// ---------------------------------------------------------------------------
__global__ void expT_kernel(const float* __restrict__ trans) {
    int i = blockIdx.x * blockDim.x + threadIdx.x;
    if (i < TT * TT) {
        int r = i >> 7;
        int c = i & (TT - 1);
        g_ET[c * TT + r] = __expf(trans[i]);
    }
}

// ---------------------------------------------------------------------------
// Kernel 2: gold score per batch
// ---------------------------------------------------------------------------
__global__ void gold_kernel(const float* __restrict__ emis,
                            const int* __restrict__ tags,
                            const float* __restrict__ trans) {
    int b = blockIdx.x;
    int tid = threadIdx.x;
    int lane = tid & 31;
    int wid = tid >> 5;

    const int stride = g_tagStride;
    const int* tg = tags + b * SS * stride;
    const float* eb = emis + (size_t)b * SS * TT;

    float sum = 0.f;
    for (int s = tid; s < SS; s += blockDim.x) {
        int cur = tg[s * stride];
        sum += eb[s * TT + cur];
        if (s < SS - 1) {
            int nxt = tg[(s + 1) * stride];
            sum += trans[cur * TT + nxt];
        }
    }
    #pragma unroll
    for (int o = 16; o > 0; o >>= 1)
        sum += __shfl_xor_sync(0xffffffffu, sum, o);
    __shared__ float red[4];
    if (lane == 0) red[wid] = sum;
    __syncthreads();
    if (tid == 0) g_gold[b] = red[0] + red[1] + red[2] + red[3];
}

// ---------------------------------------------------------------------------
// Kernel 3: forward algorithm, split-K over 2 threads per state.
// Thread k: state t = k>>1, half h = k&1, owns E[64h..64h+64) of column t.
//
// Scaled state P_s[t] = exp(alpha_s[t] - M_s), anchor M_s = alpha_{s-1}[0]
// (published one step early by thread 0, so it is available without a
//  same-step dependency). Per iteration s (consuming P_{s-1}, shift M_{s-1}):
//    acc_s[t]     = sum_i P_{s-1}[i] * E[i][t]
//    alpha_s[t]   = log(acc_s[t]) + M_{s-1} + e_s[t]
//    P_s[t]       = acc_s[t] * exp(e_s[t] + M_{s-1} - M_s)   <- exp off-path
//    thread 0 publishes M_{s+1} = alpha_s[0]                 <- logf off-path
// Registers: m_prev = M_{s-1}; moff[s&1] read after the barrier gives M_s.
// Init: M_0 = M_1 = e_0[0]; P_0[t] = exp(e_0[t] - e_0[0]).
// Final (s = SS-1): z[t] = log(acc) + m_prev + e_cur computed IN the loop,
// where m_prev is still M_{SS-2} (the shift of the consumed buffer).
// One __syncthreads per step; sp double-buffered; half 1 stored at float
// offset 68 so the two per-warp broadcast groups hit different banks.
// ---------------------------------------------------------------------------
__global__ void __launch_bounds__(256, 2) forward_kernel(const float* __restrict__ emis) {
    int b = blockIdx.x;
    int k = threadIdx.x;
    int t = k >> 1;
    int h = k & 1;
    int lane = k & 31;
    int wid = k >> 5;

    __shared__ __align__(16) float sp[2][136];   // halves at [0..64) and [68..132)
    __shared__ float moff[2];
    __shared__ float smax[8];
    __shared__ float ssum[8];

    // E half-column: 64 floats = 32 u64 pairs
    unsigned long long Ep[32];
    {
        const ulonglong2* ec = (const ulonglong2*)(g_ET + t * TT + 64 * h);
        #pragma unroll
        for (int j = 0; j < 16; j++) {
            ulonglong2 v = ec[j];
            Ep[2 * j]     = v.x;
            Ep[2 * j + 1] = v.y;
        }
    }

    const float* eb = emis + (size_t)b * SS * TT;
    const int pos = (t < 64) ? t : t + 4;        // padded store position

    // --- init: P_0 in sp[1] (read at s=1), M_1 = e_0[0] in moff[1]
    float e0 = eb[t];
    if (k == 0) moff[1] = e0;
    __syncthreads();
    float m_prev = moff[1];                      // M_0 (== M_1 == e_0[0])
    if (h == 0) sp[1][pos] = __expf(e0 - m_prev);
    float e_cur = eb[TT + t];                    // e_1[t]

    float zfin = 0.f;                            // final alpha (h==0 threads)

    for (int s = 1; s < SS; s++) {
        float e_next = (s + 1 < SS) ? eb[(s + 1) * TT + t] : 0.f;

        __syncthreads();                         // the ONLY barrier per step
        float m_new = moff[s & 1];               // M_s = alpha_{s-1}[0]
        float w = __expf(e_cur + (m_prev - m_new));  // independent of the dot

        // half-dot: acc_h = sum_{i in half} P_{s-1}[i] * E[i][t]
        const ulonglong2* pbuf = (const ulonglong2*)(sp[s & 1] + 68 * h);
        unsigned long long a0 = 0ull, a1 = 0ull, a2 = 0ull, a3 = 0ull;
        #pragma unroll
        for (int j = 0; j < 16; j += 2) {
            ulonglong2 pv = pbuf[j];
            ulonglong2 pw = pbuf[j + 1];
            asm("fma.rn.f32x2 %0, %1, %2, %0;" : "+l"(a0) : "l"(pv.x), "l"(Ep[2 * j]));
            asm("fma.rn.f32x2 %0, %1, %2, %0;" : "+l"(a1) : "l"(pv.y), "l"(Ep[2 * j + 1]));
            asm("fma.rn.f32x2 %0, %1, %2, %0;" : "+l"(a2) : "l"(pw.x), "l"(Ep[2 * j + 2]));
            asm("fma.rn.f32x2 %0, %1, %2, %0;" : "+l"(a3) : "l"(pw.y), "l"(Ep[2 * j + 3]));
        }
        float l0, h0, l1, h1, l2, h2, l3, h3;
        asm("mov.b64 {%0,%1}, %2;" : "=f"(l0), "=f"(h0) : "l"(a0));
        asm("mov.b64 {%0,%1}, %2;" : "=f"(l1), "=f"(h1) : "l"(a1));
        asm("mov.b64 {%0,%1}, %2;" : "=f"(l2), "=f"(h2) : "l"(a2));
        asm("mov.b64 {%0,%1}, %2;" : "=f"(l3), "=f"(h3) : "l"(a3));
        float acc_h = ((l0 + h0) + (l1 + h1)) + ((l2 + h2) + (l3 + h3));

        // both threads of the pair end up with the full dot
        float acc = acc_h + __shfl_xor_sync(0xffffffffu, acc_h, 1);

        if (s == SS - 1) {
            // alpha_{SS-1}[t]; m_prev is still M_{SS-2}, e_cur = e_{SS-1}[t]
            zfin = __logf(acc) + m_prev + e_cur;
            break;
        }

        if (h == 0) sp[(s + 1) & 1][pos] = acc * w;                    // P_s[t]
        if (k == 0) moff[(s + 1) & 1] = __logf(acc) + m_prev + e_cur;  // M_{s+1}

        m_prev = m_new;
        e_cur = e_next;
    }

    // ---- logZ = logsumexp_t alpha_{SS-1}[t]  (h==0 threads hold z) ----
    float z = (h == 0) ? zfin : -1e30f;

    float mx = z;
    #pragma unroll
    for (int o = 16; o > 0; o >>= 1)
        mx = fmaxf(mx, __shfl_xor_sync(0xffffffffu, mx, o));
    if (lane == 0) smax[wid] = mx;
    __syncthreads();
    mx = smax[0];
    #pragma unroll
    for (int wv = 1; wv < 8; wv++) mx = fmaxf(mx, smax[wv]);

    float v = (h == 0) ? __expf(z - mx) : 0.f;
    #pragma unroll
    for (int o = 16; o > 0; o >>= 1)
        v += __shfl_xor_sync(0xffffffffu, v, o);
    if (lane == 0) ssum[wid] = v;
    __syncthreads();
    if (k == 0) {
        float total = 0.f;
        #pragma unroll
        for (int wv = 0; wv < 8; wv++) total += ssum[wv];
        g_logZ[b] = __logf(total) + mx;
    }
}

// ---------------------------------------------------------------------------
// Kernel 4: final scalar: mean_b(-gold[b] + logZ[b])
// ---------------------------------------------------------------------------
__global__ void finalize_kernel(float* __restrict__ out) {
    int t = threadIdx.x;   // 256 threads
    int lane = t & 31;
    int wid = t >> 5;

    float v = -g_gold[t] + g_logZ[t];
    #pragma unroll
    for (int o = 16; o > 0; o >>= 1)
        v += __shfl_xor_sync(0xffffffffu, v, o);
    __shared__ float red[8];
    if (lane == 0) red[wid] = v;
    __syncthreads();
    if (t == 0) {
        float total = 0.f;
        #pragma unroll
        for (int w = 0; w < 8; w++) total += red[w];
        out[0] = total / (float)BB;
    }
}

// ---------------------------------------------------------------------------
extern "C" void kernel_launch(void* const* d_in, const int* in_sizes, int n_in,
                              void* d_out, int out_size) {
    const float* emis  = (const float*)d_in[0];   // (256, 512, 128) f32
    const int*   tags  = (const int*)d_in[1];     // (256, 512) i32/i64 (detected)
    const float* trans = (const float*)d_in[2];   // (128, 128) f32
    float* out = (float*)d_out;

    detect_tags_kernel<<<1, 32>>>((const unsigned int*)tags);
    expT_kernel<<<(TT * TT + 127) / 128, 128>>>(trans);
    gold_kernel<<<BB, 128>>>(emis, tags, trans);
    forward_kernel<<<BB, 256>>>(emis);
    finalize_kernel<<<1, BB>>>(out);
}